// round 13
// baseline (speedup 1.0000x reference)
#include <cuda_runtime.h>
#include <math.h>

#define NCAT   1024
#define INDIM  1024
#define HDIM   2048
#define GDIM   (4 * HDIM)      // 8192
#define OUTDIM 32000
#define WOUT_K (NCAT + HDIM)   // 3072

// K1: 512 gates0 + 512 gates1-base + 1500 logits-cat (rows 0..23999)
#define K1_BLOCKS 2524
// K2: 512 w_ih_l1 blocks + 500 logits-cat blocks (rows 24000..31999)
#define K2_D 512
#define K2_BLOCKS 1012
// K3: 2000 blocks (16 logits rows each)
#define K3_BLOCKS 2000

// Scratch (no allocations allowed)
__device__ float g_gates0[GDIM];
__device__ float g_gates1[GDIM];
__device__ float g_h1[HDIM];
__device__ float g_h2[HDIM];
__device__ float g_logits[OUTDIM];
__device__ float g_pmax[K3_BLOCKS];
__device__ float g_psum[K3_BLOCKS];
__device__ float g_lse;
__device__ unsigned int g_cnt0 = 0, g_cnt1 = 0, g_cnt2 = 0;

__device__ __forceinline__ float f4dot(float4 a, float4 b) {
    return a.x * b.x + a.y * b.y + a.z * b.z + a.w * b.w;
}
__device__ __forceinline__ float warp_reduce(float acc) {
#pragma unroll
    for (int off = 16; off; off >>= 1)
        acc += __shfl_down_sync(0xffffffffu, acc, off);
    return acc;
}
__device__ __forceinline__ float fast_sigmoid(float x) {
    return 1.0f / (1.0f + __expf(-x));
}
__device__ __forceinline__ float fast_tanh(float x) {
    return 1.0f - 2.0f / (__expf(2.0f * x) + 1.0f);
}
// true for whole block if last of `total` to arrive; self-resetting.
__device__ __forceinline__ bool block_is_last(unsigned int* cnt, unsigned int total) {
    __shared__ bool is_last;
    __syncthreads();
    if (threadIdx.x == 0) {
        __threadfence();
        unsigned int v = atomicAdd(cnt, 1u);
        is_last = (v == total - 1u);
        if (is_last) *cnt = 0u;
    }
    __syncthreads();
    return is_last;
}

// ---------------------------------------------------------------------------
// K1: gates0 (fused cell0) + gates1-base + logits-cat rows [0, 24000)
__global__ void __launch_bounds__(256, 4) k1_input_matvecs(
    const float* __restrict__ cat, const float* __restrict__ inp,
    const float* __restrict__ hidden, const float* __restrict__ cell,
    const float* __restrict__ w_ih_l0, const float* __restrict__ w_hh_l0,
    const float* __restrict__ b_ih_l0, const float* __restrict__ b_hh_l0,
    const float* __restrict__ w_hh_l1,
    const float* __restrict__ b_ih_l1, const float* __restrict__ b_hh_l1,
    const float* __restrict__ w_out, const float* __restrict__ b_out,
    float* __restrict__ out_h1, float* __restrict__ out_c1)
{
    int W = (blockIdx.x * blockDim.x + threadIdx.x) >> 5;
    int lane = threadIdx.x & 31;

    if (W < GDIM / 2) {
        int r0 = 2 * W, r1 = r0 + 1;
        const float4* a0 = (const float4*)(w_ih_l0 + (size_t)r0 * 2048);
        const float4* a1 = (const float4*)(w_ih_l0 + (size_t)r1 * 2048);
        const float4* h0 = (const float4*)(w_hh_l0 + (size_t)r0 * 2048);
        const float4* h1 = (const float4*)(w_hh_l0 + (size_t)r1 * 2048);
        const float4* vc = (const float4*)cat;
        const float4* vi = (const float4*)inp;
        const float4* vh = (const float4*)hidden;
        float acc0 = 0.f, acc1 = 0.f;
#pragma unroll
        for (int i = 0; i < 8; i++) {
            float4 x = vc[lane + 32 * i];
            acc0 += f4dot(__ldcs(&a0[lane + 32 * i]), x);
            acc1 += f4dot(__ldcs(&a1[lane + 32 * i]), x);
        }
#pragma unroll
        for (int i = 0; i < 8; i++) {
            float4 x = vi[lane + 32 * i];
            acc0 += f4dot(__ldcs(&a0[256 + lane + 32 * i]), x);
            acc1 += f4dot(__ldcs(&a1[256 + lane + 32 * i]), x);
        }
#pragma unroll
        for (int i = 0; i < 16; i++) {
            float4 x = vh[lane + 32 * i];
            acc0 += f4dot(__ldcs(&h0[lane + 32 * i]), x);
            acc1 += f4dot(__ldcs(&h1[lane + 32 * i]), x);
        }
        acc0 = warp_reduce(acc0);
        acc1 = warp_reduce(acc1);
        if (lane == 0) {
            g_gates0[r0] = acc0 + b_ih_l0[r0] + b_hh_l0[r0];
            g_gates0[r1] = acc1 + b_ih_l0[r1] + b_hh_l0[r1];
        }
        // cell0 in the last gates0 block — overlaps with logits-cat blocks.
        if (block_is_last(&g_cnt0, GDIM / 16)) {
            __threadfence();
            for (int j = threadIdx.x; j < HDIM; j += blockDim.x) {
                float ig = fast_sigmoid(g_gates0[j]);
                float fg = fast_sigmoid(g_gates0[HDIM + j]);
                float gg = fast_tanh(g_gates0[2 * HDIM + j]);
                float og = fast_sigmoid(g_gates0[3 * HDIM + j]);
                float c_new = fg * cell[j] + ig * gg;
                float h_new = og * fast_tanh(c_new);
                g_h1[j] = h_new;
                out_h1[j] = h_new;
                out_c1[j] = c_new;
            }
        }
    } else if (W < GDIM) {
        int r0 = 2 * (W - GDIM / 2), r1 = r0 + 1;
        const float4* w0 = (const float4*)(w_hh_l1 + (size_t)r0 * 2048);
        const float4* w1 = (const float4*)(w_hh_l1 + (size_t)r1 * 2048);
        const float4* vh = (const float4*)(hidden + HDIM);
        float acc0 = 0.f, acc1 = 0.f;
#pragma unroll
        for (int i = 0; i < 16; i++) {
            float4 x = vh[lane + 32 * i];
            acc0 += f4dot(__ldcs(&w0[lane + 32 * i]), x);
            acc1 += f4dot(__ldcs(&w1[lane + 32 * i]), x);
        }
        acc0 = warp_reduce(acc0);
        acc1 = warp_reduce(acc1);
        if (lane == 0) {
            g_gates1[r0] = acc0 + b_ih_l1[r0] + b_hh_l1[r0];
            g_gates1[r1] = acc1 + b_ih_l1[r1] + b_hh_l1[r1];
        }
    } else {
        int r0 = 2 * (W - GDIM);   // rows [0, 24000)
        int r1 = r0 + 1;
        const float4* w0 = (const float4*)(w_out + (size_t)r0 * WOUT_K);
        const float4* w1 = (const float4*)(w_out + (size_t)r1 * WOUT_K);
        const float4* vc = (const float4*)cat;
        float acc0 = 0.f, acc1 = 0.f;
#pragma unroll
        for (int i = 0; i < 8; i++) {
            float4 x = vc[lane + 32 * i];
            acc0 += f4dot(__ldcs(&w0[lane + 32 * i]), x);
            acc1 += f4dot(__ldcs(&w1[lane + 32 * i]), x);
        }
        acc0 = warp_reduce(acc0);
        acc1 = warp_reduce(acc1);
        if (lane == 0) {
            g_logits[r0] = acc0 + b_out[r0];
            g_logits[r1] = acc1 + b_out[r1];
        }
    }
}

// ---------------------------------------------------------------------------
// K2: blocks [0,512): gates1 += w_ih_l1 @ h1 (last one runs cell1, overlapped)
//     blocks [512,1012): logits-cat rows [24000, 32000)
__global__ void __launch_bounds__(256, 4) k2_l1_and_cat(
    const float* __restrict__ w_ih_l1, const float* __restrict__ cell,
    const float* __restrict__ cat,
    const float* __restrict__ w_out, const float* __restrict__ b_out,
    float* __restrict__ out_h2, float* __restrict__ out_c2)
{
    int b = blockIdx.x;
    int lane = threadIdx.x & 31;
    int wlocal = threadIdx.x >> 5;

    if (b < K2_D) {
        int r0 = (b * 8 + wlocal) * 2, r1 = r0 + 1;
        const float4* w0 = (const float4*)(w_ih_l1 + (size_t)r0 * 2048);
        const float4* w1 = (const float4*)(w_ih_l1 + (size_t)r1 * 2048);
        const float4* vh = (const float4*)g_h1;
        float acc0 = 0.f, acc1 = 0.f;
#pragma unroll
        for (int i = 0; i < 16; i++) {
            float4 x = vh[lane + 32 * i];
            acc0 += f4dot(__ldcs(&w0[lane + 32 * i]), x);
            acc1 += f4dot(__ldcs(&w1[lane + 32 * i]), x);
        }
        acc0 = warp_reduce(acc0);
        acc1 = warp_reduce(acc1);
        if (lane == 0) {
            g_gates1[r0] += acc0;
            g_gates1[r1] += acc1;
        }
        // cell1 in the last D block — overlaps with the cat-filler blocks.
        if (block_is_last(&g_cnt1, K2_D)) {
            __threadfence();
            for (int j = threadIdx.x; j < HDIM; j += blockDim.x) {
                float ig = fast_sigmoid(g_gates1[j]);
                float fg = fast_sigmoid(g_gates1[HDIM + j]);
                float gg = fast_tanh(g_gates1[2 * HDIM + j]);
                float og = fast_sigmoid(g_gates1[3 * HDIM + j]);
                float c_new = fg * cell[HDIM + j] + ig * gg;
                float h_new = og * fast_tanh(c_new);
                g_h2[j] = h_new;
                out_h2[j] = h_new;
                out_c2[j] = c_new;
            }
        }
    } else {
        int r0 = 24000 + ((b - K2_D) * 8 + wlocal) * 2;
        int r1 = r0 + 1;
        const float4* w0 = (const float4*)(w_out + (size_t)r0 * WOUT_K);
        const float4* w1 = (const float4*)(w_out + (size_t)r1 * WOUT_K);
        const float4* vc = (const float4*)cat;
        float acc0 = 0.f, acc1 = 0.f;
#pragma unroll
        for (int i = 0; i < 8; i++) {
            float4 x = vc[lane + 32 * i];
            acc0 += f4dot(__ldcs(&w0[lane + 32 * i]), x);
            acc1 += f4dot(__ldcs(&w1[lane + 32 * i]), x);
        }
        acc0 = warp_reduce(acc0);
        acc1 = warp_reduce(acc1);
        if (lane == 0) {
            g_logits[r0] = acc0 + b_out[r0];
            g_logits[r1] = acc1 + b_out[r1];
        }
    }
}

// ---------------------------------------------------------------------------
// K3: g_logits += w_out[:, 1024:3072] @ h2; per-block softmax partial in the
// epilogue; last block folds all partials into g_lse.
__global__ void __launch_bounds__(256, 4) k3_out_h(const float* __restrict__ w_out)
{
    __shared__ float s_vals[16];
    __shared__ float red[8];
    int b = blockIdx.x;
    int lane = threadIdx.x & 31;
    int wlocal = threadIdx.x >> 5;
    int r0 = (b * 8 + wlocal) * 2, r1 = r0 + 1;

    const float4* w0 = (const float4*)(w_out + (size_t)r0 * WOUT_K + NCAT);
    const float4* w1 = (const float4*)(w_out + (size_t)r1 * WOUT_K + NCAT);
    const float4* vh = (const float4*)g_h2;
    float acc0 = 0.f, acc1 = 0.f;
#pragma unroll
    for (int i = 0; i < 16; i++) {
        float4 x = vh[lane + 32 * i];
        acc0 += f4dot(__ldcs(&w0[lane + 32 * i]), x);
        acc1 += f4dot(__ldcs(&w1[lane + 32 * i]), x);
    }
    acc0 = warp_reduce(acc0);
    acc1 = warp_reduce(acc1);
    if (lane == 0) {
        float v0 = g_logits[r0] + acc0;
        float v1 = g_logits[r1] + acc1;
        g_logits[r0] = v0;
        g_logits[r1] = v1;
        s_vals[2 * wlocal]     = v0;
        s_vals[2 * wlocal + 1] = v1;
    }
    __syncthreads();
    // warp 0: partial (max, sum-exp) over this block's 16 logits
    if (wlocal == 0) {
        float v = (lane < 16) ? s_vals[lane] : -INFINITY;
        float m = v;
#pragma unroll
        for (int off = 16; off; off >>= 1)
            m = fmaxf(m, __shfl_xor_sync(0xffffffffu, m, off));
        float e = (lane < 16) ? __expf(v - m) : 0.f;
#pragma unroll
        for (int off = 16; off; off >>= 1)
            e += __shfl_xor_sync(0xffffffffu, e, off);
        if (lane == 0) { g_pmax[b] = m; g_psum[b] = e; }
    }
    // last block: fold 2000 partials into lse
    if (block_is_last(&g_cnt2, K3_BLOCKS)) {
        __threadfence();
        int tid = threadIdx.x;
        float m = -INFINITY;
        for (int i = tid; i < K3_BLOCKS; i += 256) m = fmaxf(m, g_pmax[i]);
#pragma unroll
        for (int off = 16; off; off >>= 1)
            m = fmaxf(m, __shfl_xor_sync(0xffffffffu, m, off));
        if (lane == 0) red[wlocal] = m;
        __syncthreads();
        if (wlocal == 0) {
            float v = (lane < 8) ? red[lane] : -INFINITY;
#pragma unroll
            for (int off = 4; off; off >>= 1)
                v = fmaxf(v, __shfl_xor_sync(0xffffffffu, v, off));
            if (lane == 0) red[0] = v;
        }
        __syncthreads();
        m = red[0];
        __syncthreads();
        float s = 0.f;
        for (int i = tid; i < K3_BLOCKS; i += 256)
            s += g_psum[i] * __expf(g_pmax[i] - m);
#pragma unroll
        for (int off = 16; off; off >>= 1)
            s += __shfl_xor_sync(0xffffffffu, s, off);
        if (lane == 0) red[wlocal] = s;
        __syncthreads();
        if (wlocal == 0) {
            float v = (lane < 8) ? red[lane] : 0.f;
#pragma unroll
            for (int off = 4; off; off >>= 1)
                v += __shfl_xor_sync(0xffffffffu, v, off);
            if (lane == 0) g_lse = m + __logf(v);
        }
    }
}

// ---------------------------------------------------------------------------
// Finalize: out = logits - lse
__global__ void softmax_finalize(float* __restrict__ out) {
    int i = blockIdx.x * 256 + threadIdx.x;
    if (i < OUTDIM) out[i] = g_logits[i] - g_lse;
}

// ---------------------------------------------------------------------------
extern "C" void kernel_launch(void* const* d_in, const int* in_sizes, int n_in,
                              void* d_out, int out_size) {
    const float* category = (const float*)d_in[0];
    const float* input    = (const float*)d_in[1];
    const float* hidden   = (const float*)d_in[2];
    const float* cell     = (const float*)d_in[3];
    const float* w_ih_l0  = (const float*)d_in[4];
    const float* w_hh_l0  = (const float*)d_in[5];
    const float* b_ih_l0  = (const float*)d_in[6];
    const float* b_hh_l0  = (const float*)d_in[7];
    const float* w_ih_l1  = (const float*)d_in[8];
    const float* w_hh_l1  = (const float*)d_in[9];
    const float* b_ih_l1  = (const float*)d_in[10];
    const float* b_hh_l1  = (const float*)d_in[11];
    const float* w_out    = (const float*)d_in[12];
    const float* b_out    = (const float*)d_in[13];

    float* out = (float*)d_out;
    float* out_logp = out;
    float* out_h1 = out + OUTDIM;
    float* out_h2 = out + OUTDIM + HDIM;
    float* out_c1 = out + OUTDIM + 2 * HDIM;
    float* out_c2 = out + OUTDIM + 3 * HDIM;

    // K1: 2524 blocks = 512 gates0 + 512 gates1-base + 1500 logits-cat
    k1_input_matvecs<<<K1_BLOCKS, 256>>>(
        category, input, hidden, cell,
        w_ih_l0, w_hh_l0, b_ih_l0, b_hh_l0,
        w_hh_l1, b_ih_l1, b_hh_l1,
        w_out, b_out, out_h1, out_c1);

    // K2: 1012 blocks = 512 w_ih_l1 (+fused cell1) + 500 logits-cat
    k2_l1_and_cat<<<K2_BLOCKS, 256>>>(w_ih_l1, cell, category, w_out, b_out,
                                      out_h2, out_c2);

    // K3: 2000 blocks, fused softmax partials + lse fold
    k3_out_h<<<K3_BLOCKS, 256>>>(w_out);

    // finalize: out = logits - lse
    softmax_finalize<<<(OUTDIM + 255) / 256, 256>>>(out_logp);
}

// round 15
// speedup vs baseline: 1.1017x; 1.1017x over previous
#include <cuda_runtime.h>
#include <math.h>

#define NCAT   1024
#define INDIM  1024
#define HDIM   2048
#define GDIM   (4 * HDIM)      // 8192
#define OUTDIM 32000
#define WOUT_K (NCAT + HDIM)   // 3072

#define SMX_CHUNKS 64
#define SMX_CHUNK  (OUTDIM / SMX_CHUNKS)  // 500

// Scratch (no allocations allowed)
__device__ float g_gates0[GDIM];
__device__ float g_gates1[GDIM];
__device__ float g_h1[HDIM];
__device__ float g_h2[HDIM];
__device__ float g_logits[OUTDIM];
__device__ float g_pmax[SMX_CHUNKS];
__device__ float g_psum[SMX_CHUNKS];
__device__ unsigned int g_cnt0 = 0;

__device__ __forceinline__ float f4dot(float4 a, float4 b) {
    return a.x * b.x + a.y * b.y + a.z * b.z + a.w * b.w;
}
__device__ __forceinline__ float warp_reduce(float acc) {
#pragma unroll
    for (int off = 16; off; off >>= 1)
        acc += __shfl_down_sync(0xffffffffu, acc, off);
    return acc;
}
__device__ __forceinline__ float fast_sigmoid(float x) {
    return 1.0f / (1.0f + __expf(-x));
}
__device__ __forceinline__ float fast_tanh(float x) {
    return 1.0f - 2.0f / (__expf(2.0f * x) + 1.0f);
}

// ---------------------------------------------------------------------------
// K1: all input-only matvecs, 2 rows per warp.  (identical to R11)
__global__ void __launch_bounds__(256, 4) k1_input_matvecs(
    const float* __restrict__ cat, const float* __restrict__ inp,
    const float* __restrict__ hidden, const float* __restrict__ cell,
    const float* __restrict__ w_ih_l0, const float* __restrict__ w_hh_l0,
    const float* __restrict__ b_ih_l0, const float* __restrict__ b_hh_l0,
    const float* __restrict__ w_hh_l1,
    const float* __restrict__ b_ih_l1, const float* __restrict__ b_hh_l1,
    const float* __restrict__ w_out, const float* __restrict__ b_out,
    float* __restrict__ out_h1, float* __restrict__ out_c1)
{
    int W = (blockIdx.x * blockDim.x + threadIdx.x) >> 5;
    int lane = threadIdx.x & 31;

    if (W < GDIM / 2) {
        int r0 = 2 * W, r1 = r0 + 1;
        const float4* a0 = (const float4*)(w_ih_l0 + (size_t)r0 * 2048);
        const float4* a1 = (const float4*)(w_ih_l0 + (size_t)r1 * 2048);
        const float4* h0 = (const float4*)(w_hh_l0 + (size_t)r0 * 2048);
        const float4* h1 = (const float4*)(w_hh_l0 + (size_t)r1 * 2048);
        const float4* vc = (const float4*)cat;
        const float4* vi = (const float4*)inp;
        const float4* vh = (const float4*)hidden;
        float acc0 = 0.f, acc1 = 0.f;
#pragma unroll
        for (int i = 0; i < 8; i++) {
            float4 x = vc[lane + 32 * i];
            acc0 += f4dot(__ldcs(&a0[lane + 32 * i]), x);
            acc1 += f4dot(__ldcs(&a1[lane + 32 * i]), x);
        }
#pragma unroll
        for (int i = 0; i < 8; i++) {
            float4 x = vi[lane + 32 * i];
            acc0 += f4dot(__ldcs(&a0[256 + lane + 32 * i]), x);
            acc1 += f4dot(__ldcs(&a1[256 + lane + 32 * i]), x);
        }
#pragma unroll
        for (int i = 0; i < 16; i++) {
            float4 x = vh[lane + 32 * i];
            acc0 += f4dot(__ldcs(&h0[lane + 32 * i]), x);
            acc1 += f4dot(__ldcs(&h1[lane + 32 * i]), x);
        }
        acc0 = warp_reduce(acc0);
        acc1 = warp_reduce(acc1);
        if (lane == 0) {
            g_gates0[r0] = acc0 + b_ih_l0[r0] + b_hh_l0[r0];
            g_gates0[r1] = acc1 + b_ih_l0[r1] + b_hh_l0[r1];
        }

        // cell0 in the last gates0 block — overlaps with logits-cat blocks.
        __shared__ bool is_last;
        __syncthreads();
        if (threadIdx.x == 0) {
            __threadfence();
            unsigned int v = atomicAdd(&g_cnt0, 1u);
            is_last = (v == (GDIM / 16) - 1u);
            if (is_last) g_cnt0 = 0u;
        }
        __syncthreads();
        if (is_last) {
            for (int j = threadIdx.x; j < HDIM; j += blockDim.x) {
                float ig = fast_sigmoid(g_gates0[j]);
                float fg = fast_sigmoid(g_gates0[HDIM + j]);
                float gg = fast_tanh(g_gates0[2 * HDIM + j]);
                float og = fast_sigmoid(g_gates0[3 * HDIM + j]);
                float c_new = fg * cell[j] + ig * gg;
                float h_new = og * fast_tanh(c_new);
                g_h1[j] = h_new;
                out_h1[j] = h_new;
                out_c1[j] = c_new;
            }
        }
    } else if (W < GDIM) {
        int r0 = 2 * (W - GDIM / 2), r1 = r0 + 1;
        const float4* w0 = (const float4*)(w_hh_l1 + (size_t)r0 * 2048);
        const float4* w1 = (const float4*)(w_hh_l1 + (size_t)r1 * 2048);
        const float4* vh = (const float4*)(hidden + HDIM);
        float acc0 = 0.f, acc1 = 0.f;
#pragma unroll
        for (int i = 0; i < 16; i++) {
            float4 x = vh[lane + 32 * i];
            acc0 += f4dot(__ldcs(&w0[lane + 32 * i]), x);
            acc1 += f4dot(__ldcs(&w1[lane + 32 * i]), x);
        }
        acc0 = warp_reduce(acc0);
        acc1 = warp_reduce(acc1);
        if (lane == 0) {
            g_gates1[r0] = acc0 + b_ih_l1[r0] + b_hh_l1[r0];
            g_gates1[r1] = acc1 + b_ih_l1[r1] + b_hh_l1[r1];
        }
    } else {
        int r0 = 2 * (W - GDIM);
        if (r0 < OUTDIM) {
            int r1 = r0 + 1;
            const float4* w0 = (const float4*)(w_out + (size_t)r0 * WOUT_K);
            const float4* w1 = (const float4*)(w_out + (size_t)r1 * WOUT_K);
            const float4* vc = (const float4*)cat;
            float acc0 = 0.f, acc1 = 0.f;
#pragma unroll
            for (int i = 0; i < 8; i++) {
                float4 x = vc[lane + 32 * i];
                acc0 += f4dot(__ldcs(&w0[lane + 32 * i]), x);
                acc1 += f4dot(__ldcs(&w1[lane + 32 * i]), x);
            }
            acc0 = warp_reduce(acc0);
            acc1 = warp_reduce(acc1);
            if (lane == 0) {
                g_logits[r0] = acc0 + b_out[r0];
                g_logits[r1] = acc1 + b_out[r1];
            }
        }
    }
}

// ---------------------------------------------------------------------------
// K2: g_gates1 += w_ih_l1 @ h1, 2 rows/warp.  (identical to R11)
__global__ void __launch_bounds__(256, 4) k2_l1_ih(const float* __restrict__ w_ih_l1)
{
    int W = (blockIdx.x * blockDim.x + threadIdx.x) >> 5;
    int lane = threadIdx.x & 31;
    int r0 = 2 * W, r1 = r0 + 1;
    const float4* w0 = (const float4*)(w_ih_l1 + (size_t)r0 * 2048);
    const float4* w1 = (const float4*)(w_ih_l1 + (size_t)r1 * 2048);
    const float4* vh = (const float4*)g_h1;
    float acc0 = 0.f, acc1 = 0.f;
#pragma unroll
    for (int i = 0; i < 16; i++) {
        float4 x = vh[lane + 32 * i];
        acc0 += f4dot(__ldcs(&w0[lane + 32 * i]), x);
        acc1 += f4dot(__ldcs(&w1[lane + 32 * i]), x);
    }
    acc0 = warp_reduce(acc0);
    acc1 = warp_reduce(acc1);
    if (lane == 0) {
        g_gates1[r0] += acc0;
        g_gates1[r1] += acc1;
    }
}

// ---------------------------------------------------------------------------
// cell1  (identical to R11)
__global__ void lstm_cell1_kernel(const float* __restrict__ cell,
                                  float* __restrict__ out_h2,
                                  float* __restrict__ out_c2) {
    int j = blockIdx.x * blockDim.x + threadIdx.x;
    if (j >= HDIM) return;
    float ig = fast_sigmoid(g_gates1[j]);
    float fg = fast_sigmoid(g_gates1[HDIM + j]);
    float gg = fast_tanh(g_gates1[2 * HDIM + j]);
    float og = fast_sigmoid(g_gates1[3 * HDIM + j]);
    float c_new = fg * cell[HDIM + j] + ig * gg;
    float h_new = og * fast_tanh(c_new);
    g_h2[j] = h_new;
    out_h2[j] = h_new;
    out_c2[j] = c_new;
}

// ---------------------------------------------------------------------------
// K3: g_logits += w_out[:, 1024:3072] @ h2 — 4 rows/warp (the experiment).
__global__ void __launch_bounds__(256) k3_out_h(const float* __restrict__ w_out)
{
    int W = (blockIdx.x * blockDim.x + threadIdx.x) >> 5;
    int lane = threadIdx.x & 31;
    int r0 = 4 * W;
    if (r0 >= OUTDIM) return;
    const float4* w0 = (const float4*)(w_out + (size_t)r0 * WOUT_K + NCAT);
    const float4* w1 = (const float4*)(w_out + (size_t)(r0 + 1) * WOUT_K + NCAT);
    const float4* w2 = (const float4*)(w_out + (size_t)(r0 + 2) * WOUT_K + NCAT);
    const float4* w3 = (const float4*)(w_out + (size_t)(r0 + 3) * WOUT_K + NCAT);
    const float4* vh = (const float4*)g_h2;
    float acc0 = 0.f, acc1 = 0.f, acc2 = 0.f, acc3 = 0.f;
#pragma unroll
    for (int i = 0; i < 16; i++) {
        float4 x = vh[lane + 32 * i];
        acc0 += f4dot(__ldcs(&w0[lane + 32 * i]), x);
        acc1 += f4dot(__ldcs(&w1[lane + 32 * i]), x);
        acc2 += f4dot(__ldcs(&w2[lane + 32 * i]), x);
        acc3 += f4dot(__ldcs(&w3[lane + 32 * i]), x);
    }
    acc0 = warp_reduce(acc0);
    acc1 = warp_reduce(acc1);
    acc2 = warp_reduce(acc2);
    acc3 = warp_reduce(acc3);
    if (lane == 0) {
        g_logits[r0]     += acc0;
        g_logits[r0 + 1] += acc1;
        g_logits[r0 + 2] += acc2;
        g_logits[r0 + 3] += acc3;
    }
}

// ---------------------------------------------------------------------------
// Parallel log_softmax stage 1  (identical to R11)
__global__ void softmax_partials(void) {
    __shared__ float red[8];
    int c = blockIdx.x;
    int tid = threadIdx.x;
    int lane = tid & 31, wid = tid >> 5;
    int base = c * SMX_CHUNK;

    float m = -INFINITY;
    for (int i = tid; i < SMX_CHUNK; i += 256) m = fmaxf(m, g_logits[base + i]);
#pragma unroll
    for (int off = 16; off; off >>= 1)
        m = fmaxf(m, __shfl_xor_sync(0xffffffffu, m, off));
    if (lane == 0) red[wid] = m;
    __syncthreads();
    if (wid == 0) {
        float v = (lane < 8) ? red[lane] : -INFINITY;
#pragma unroll
        for (int off = 4; off; off >>= 1)
            v = fmaxf(v, __shfl_xor_sync(0xffffffffu, v, off));
        if (lane == 0) red[0] = v;
    }
    __syncthreads();
    m = red[0];
    __syncthreads();

    float s = 0.f;
    for (int i = tid; i < SMX_CHUNK; i += 256) s += __expf(g_logits[base + i] - m);
#pragma unroll
    for (int off = 16; off; off >>= 1)
        s += __shfl_xor_sync(0xffffffffu, s, off);
    if (lane == 0) red[wid] = s;
    __syncthreads();
    if (wid == 0) {
        float v = (lane < 8) ? red[lane] : 0.f;
#pragma unroll
        for (int off = 4; off; off >>= 1)
            v += __shfl_xor_sync(0xffffffffu, v, off);
        if (lane == 0) { g_pmax[c] = m; g_psum[c] = v; }
    }
}

// Stage 2  (identical to R11)
__global__ void softmax_finalize(float* __restrict__ out) {
    __shared__ float s_lse;
    int tid = threadIdx.x;
    if (tid < 32) {
        float m = (tid < SMX_CHUNKS) ? g_pmax[tid] : -INFINITY;
        float mm = (tid + 32 < SMX_CHUNKS) ? g_pmax[tid + 32] : -INFINITY;
        m = fmaxf(m, mm);
#pragma unroll
        for (int off = 16; off; off >>= 1)
            m = fmaxf(m, __shfl_xor_sync(0xffffffffu, m, off));
        float s = 0.f;
        if (tid < SMX_CHUNKS) s += g_psum[tid] * __expf(g_pmax[tid] - m);
        if (tid + 32 < SMX_CHUNKS) s += g_psum[tid + 32] * __expf(g_pmax[tid + 32] - m);
#pragma unroll
        for (int off = 16; off; off >>= 1)
            s += __shfl_xor_sync(0xffffffffu, s, off);
        if (tid == 0) s_lse = m + __logf(s);
    }
    __syncthreads();
    float lse = s_lse;
    int i = blockIdx.x * 256 + tid;
    if (i < OUTDIM) out[i] = g_logits[i] - lse;
}

// ---------------------------------------------------------------------------
extern "C" void kernel_launch(void* const* d_in, const int* in_sizes, int n_in,
                              void* d_out, int out_size) {
    const float* category = (const float*)d_in[0];
    const float* input    = (const float*)d_in[1];
    const float* hidden   = (const float*)d_in[2];
    const float* cell     = (const float*)d_in[3];
    const float* w_ih_l0  = (const float*)d_in[4];
    const float* w_hh_l0  = (const float*)d_in[5];
    const float* b_ih_l0  = (const float*)d_in[6];
    const float* b_hh_l0  = (const float*)d_in[7];
    const float* w_ih_l1  = (const float*)d_in[8];
    const float* w_hh_l1  = (const float*)d_in[9];
    const float* b_ih_l1  = (const float*)d_in[10];
    const float* b_hh_l1  = (const float*)d_in[11];
    const float* w_out    = (const float*)d_in[12];
    const float* b_out    = (const float*)d_in[13];

    float* out = (float*)d_out;
    float* out_logp = out;
    float* out_h1 = out + OUTDIM;
    float* out_h2 = out + OUTDIM + HDIM;
    float* out_c1 = out + OUTDIM + 2 * HDIM;
    float* out_c2 = out + OUTDIM + 3 * HDIM;

    // K1: 3024 blocks = 512 gates0 + 512 gates1-partial + 2000 logits-cat
    k1_input_matvecs<<<3024, 256>>>(
        category, input, hidden, cell,
        w_ih_l0, w_hh_l0, b_ih_l0, b_hh_l0,
        w_hh_l1, b_ih_l1, b_hh_l1,
        w_out, b_out, out_h1, out_c1);

    // K2: 8192 rows, 2 rows/warp, 8 warps/block -> 512 blocks
    k2_l1_ih<<<GDIM / 16, 256>>>(w_ih_l1);

    // cell1
    lstm_cell1_kernel<<<HDIM / 256, 256>>>(cell, out_h2, out_c2);

    // K3: 32000 rows, 4 rows/warp, 8 warps/block -> 1000 blocks
    k3_out_h<<<OUTDIM / 32, 256>>>(w_out);

    // parallel log_softmax: partials then finalize
    softmax_partials<<<SMX_CHUNKS, 256>>>();
    softmax_finalize<<<(OUTDIM + 255) / 256, 256>>>(out_logp);
}